// round 1
// baseline (speedup 1.0000x reference)
#include <cuda_runtime.h>
#include <math.h>

#define B_ 8
#define C_ 64
#define L_ 2048
#define CS_ 256
#define HD_ 64
#define NN_ (B_*CS_*L_)      // 4194304
#define NC_ (B_*C_*L_)       // 1048576
#define NEVAL_ 25

// ---------------- scratch (device globals; no runtime allocation) ----------------
__device__ float g_stacked[NN_];
__device__ float g_y[NN_];
__device__ float g_ytmp[NN_];
__device__ float g_s[6][NN_];
__device__ float g_h1[B_*HD_*L_];
__device__ float g_h2[B_*HD_*L_];
__device__ float g_apA[NC_];
__device__ float g_apB[NC_];
__device__ float g_amax[B_*C_];
__device__ float g_filt[16];
__device__ float g_gb[NEVAL_*128];
__device__ double g_part[B_*64];

__device__ __forceinline__ float gelu_f(float x){
    return 0.5f * x * (1.0f + erff(x * 0.70710678118654752440f));
}

// ---------------- wavelet part ----------------
// copy x into stacked channels [0,64)
__global__ void kcopyx(const float* __restrict__ x, float* __restrict__ stacked){
    int i = blockIdx.x*256 + threadIdx.x;      // over NC_
    int l = i & (L_-1); int bc = i >> 11; int c = bc & 63; int b = bc >> 6;
    stacked[(((b*CS_) + c) << 11) + l] = x[i];
}

// row max: one block per (b,c)
__global__ void kmax(const float* __restrict__ src, float* __restrict__ amax){
    int row = blockIdx.x;
    const float* p = src + (size_t)row * L_;
    float m = -3.4e38f;
    for (int i = threadIdx.x; i < L_; i += 256) m = fmaxf(m, p[i]);
    __shared__ float sm[256];
    sm[threadIdx.x] = m; __syncthreads();
    for (int s = 128; s > 0; s >>= 1){
        if (threadIdx.x < s) sm[threadIdx.x] = fmaxf(sm[threadIdx.x], sm[threadIdx.x+s]);
        __syncthreads();
    }
    if (threadIdx.x == 0) amax[row] = sm[0];
}

// dywan MLP -> lo/hi filters (1 block, 256 threads)
__global__ void kdywan(const float* __restrict__ amax,
                       const float* __restrict__ sw1, const float* __restrict__ sb1,
                       const float* __restrict__ sw2, const float* __restrict__ sb2,
                       const float* __restrict__ sw3, const float* __restrict__ sb3,
                       float* __restrict__ filt){
    __shared__ float feat[8*32], g2[8*32], raw[8*16], nrm[16];
    int t = threadIdx.x;
    { int b = t >> 5, h = t & 31;
      float s = sb1[h];
      const float* am = amax + b*64; const float* w = sw1 + h*64;
      #pragma unroll 8
      for (int c = 0; c < 64; c++) s += am[c]*w[c];
      feat[t] = gelu_f(s); }
    __syncthreads();
    { int b = t >> 5, h = t & 31;
      float s = sb2[h];
      #pragma unroll 8
      for (int k = 0; k < 32; k++) s += feat[b*32+k]*sw2[h*32+k];
      g2[t] = gelu_f(s); }
    __syncthreads();
    if (t < 128){ int b = t >> 4, j = t & 15;
      float s = sb3[j];
      #pragma unroll 8
      for (int k = 0; k < 32; k++) s += g2[b*32+k]*sw3[j*32+k];
      raw[t] = s; }
    __syncthreads();
    if (t < 16){ int b = t >> 1, hh = t & 1;
      float s = 0.f;
      for (int j = 0; j < 8; j++){ float v = raw[b*16 + hh*8 + j]; s += v*v; }
      nrm[t] = sqrtf(s); }
    __syncthreads();
    if (t < 16){ int hh = t >> 3, j = t & 7;
      float s = 0.f;
      for (int b = 0; b < 8; b++) s += raw[b*16 + hh*8 + j] / nrm[b*2 + hh];
      filt[hh*8 + j] = s * 0.125f; }
}

// depthwise wavelet conv with reflect pad (3 left, 4 right), FL=8
__global__ void kwav(const float* __restrict__ src, const float* __restrict__ filt,
                     float* __restrict__ apOut, float* __restrict__ stacked, int chOff){
    int i = blockIdx.x*256 + threadIdx.x;  // over NC_
    int l = i & (L_-1); int bc = i >> 11; int c = bc & 63; int b = bc >> 6;
    const float* row = src + (size_t)bc * L_;
    float alo = 0.f, ahi = 0.f;
    #pragma unroll
    for (int k = 0; k < 8; k++){
        int o = l + k - 3;
        if (o < 0) o = -o;
        if (o >= L_) o = 2*L_ - 2 - o;
        float v = row[o];
        alo += v * filt[k];
        ahi += v * filt[8 + k];
    }
    apOut[i] = alo;
    stacked[(((size_t)b*CS_ + chOff + c) << 11) + l] = ahi;
}

// ---------------- time MLP: gamma/beta for all 25 evals ----------------
__global__ void kgb(const float* __restrict__ tw1, const float* __restrict__ tb1,
                    const float* __restrict__ tw2, const float* __restrict__ tb2,
                    const float* __restrict__ cw,  const float* __restrict__ cb,
                    float* __restrict__ gb){
    int e = blockIdx.x;
    const double hs = 0.25;
    double td;
    if (e == 24) td = 1.0;
    else {
        int i = e / 6, s = e % 6;
        double off;
        switch (s){
            case 0: off = 0.0; break;
            case 1: off = hs/5.0; break;
            case 2: off = 3.0*hs/10.0; break;
            case 3: off = 4.0*hs/5.0; break;
            case 4: off = 8.0*hs/9.0; break;
            default: off = hs; break;
        }
        td = (double)i*hs + off;
    }
    float t = (float)td;
    __shared__ float te1[16], te2[16];
    int tid = threadIdx.x;
    if (tid < 16) te1[tid] = gelu_f(t * tw1[tid] + tb1[tid]);
    __syncthreads();
    if (tid < 16){
        float s = tb2[tid];
        #pragma unroll
        for (int k = 0; k < 16; k++) s += te1[k]*tw2[tid*16+k];
        te2[tid] = s;
    }
    __syncthreads();
    float s = cb[tid];
    #pragma unroll
    for (int k = 0; k < 16; k++) s += te2[k]*cw[tid*16+k];
    gb[e*128 + tid] = s;
}

// ---------------- K=3 conv1d (pad=1), smem tiled ----------------
// block (32 l, 8 co); grid (L/32, B, COUT/8)
template<int CIN, int CIC, bool FILM, bool DOGELU>
__global__ void kconv(const float* __restrict__ in, const float* __restrict__ w,
                      const float* __restrict__ bias, const float* __restrict__ gb,
                      float* __restrict__ out, int coTotal){
    __shared__ float xs[CIC][34];
    __shared__ float ws[8][CIC][3];
    int b = blockIdx.y;
    int lbase = blockIdx.x * 32;
    int cobase = blockIdx.z * 8;
    int tx = threadIdx.x, ty = threadIdx.y;
    int t = ty*32 + tx;
    float acc = 0.f;
    for (int c0 = 0; c0 < CIN; c0 += CIC){
        for (int idx = t; idx < CIC*34; idx += 256){
            int ci = idx / 34, j = idx - ci*34;
            int gl = lbase - 1 + j;
            float v = 0.f;
            if (gl >= 0 && gl < L_) v = in[((size_t)(b*CIN + c0 + ci)) * L_ + gl];
            xs[ci][j] = v;
        }
        for (int idx = t; idx < 8*CIC*3; idx += 256){
            int col = idx / (CIC*3);
            int r = idx - col*CIC*3;
            int ci = r / 3, k = r - ci*3;
            ws[col][ci][k] = w[((size_t)(cobase + col)*CIN + c0 + ci)*3 + k];
        }
        __syncthreads();
        #pragma unroll 8
        for (int ci = 0; ci < CIC; ci++){
            float x0 = xs[ci][tx], x1 = xs[ci][tx+1], x2 = xs[ci][tx+2];
            acc += x0*ws[ty][ci][0];
            acc += x1*ws[ty][ci][1];
            acc += x2*ws[ty][ci][2];
        }
        __syncthreads();
    }
    int co = cobase + ty;
    float h = acc + bias[co];
    if (FILM) h = (1.f + gb[co]) * h + gb[64 + co];
    if (DOGELU) h = gelu_f(h);
    out[((size_t)(b*coTotal + co)) * L_ + lbase + tx] = h;
}

// ---------------- stage combination: dst = y + sum ck*sk ----------------
__global__ void kcomb(float* __restrict__ dst, const float* __restrict__ y,
                      const float* __restrict__ s1, float c1,
                      const float* __restrict__ s2, float c2,
                      const float* __restrict__ s3, float c3,
                      const float* __restrict__ s4, float c4,
                      const float* __restrict__ s5, float c5,
                      const float* __restrict__ s6, float c6){
    int i = blockIdx.x*256 + threadIdx.x;
    float v = y[i] + c1*s1[i];
    if (s2) v += c2*s2[i];
    if (s3) v += c3*s3[i];
    if (s4) v += c4*s4[i];
    if (s5) v += c5*s5[i];
    if (s6) v += c6*s6[i];
    dst[i] = v;
}

// ---------------- ecloss reduction ----------------
__global__ void kinner(const float* __restrict__ a, const float* __restrict__ d,
                       double* __restrict__ part){
    int bb = blockIdx.x, ch = blockIdx.y;
    size_t base = (size_t)bb*CS_*L_ + (size_t)ch*8192;
    double s = 0.0;
    for (int i = threadIdx.x; i < 8192; i += 256)
        s += (double)a[base+i] * (double)d[base+i];
    __shared__ double sm[256];
    sm[threadIdx.x] = s; __syncthreads();
    for (int st = 128; st > 0; st >>= 1){
        if (threadIdx.x < st) sm[threadIdx.x] += sm[threadIdx.x+st];
        __syncthreads();
    }
    if (threadIdx.x == 0) part[bb*64 + ch] = sm[0];
}

__global__ void kfinal(const double* __restrict__ part, float* __restrict__ out){
    if (threadIdx.x == 0){
        double acc = 0.0;
        for (int b = 0; b < 8; b++){
            double s = 0.0;
            for (int j = 0; j < 64; j++) s += part[b*64+j];
            acc += s*s;
        }
        out[4194304] = (float)(acc / 8.0);
    }
}

// ---------------- output permute: (yl,yh0,yh1,yh2) concat ----------------
__global__ void kout(const float* __restrict__ y, float* __restrict__ out){
    int i = blockIdx.x*256 + threadIdx.x;  // over NN_
    int l = i & (L_-1); int bc = i >> 11; int c = bc & 255; int b = bc >> 8;
    int g = c >> 6; int cc = c & 63;
    out[(size_t)g*(B_*C_*L_) + (((size_t)b*C_ + cc) << 11) + l] = y[i];
}

// ---------------- host orchestration ----------------
extern "C" void kernel_launch(void* const* d_in, const int* in_sizes, int n_in,
                              void* d_out, int out_size){
    const float* x   = (const float*)d_in[0];
    const float* sw1 = (const float*)d_in[1];
    const float* sb1 = (const float*)d_in[2];
    const float* sw2 = (const float*)d_in[3];
    const float* sb2 = (const float*)d_in[4];
    const float* sw3 = (const float*)d_in[5];
    const float* sb3 = (const float*)d_in[6];
    const float* tw1 = (const float*)d_in[7];
    const float* tb1 = (const float*)d_in[8];
    const float* tw2 = (const float*)d_in[9];
    const float* tb2 = (const float*)d_in[10];
    const float* cw  = (const float*)d_in[11];
    const float* cb  = (const float*)d_in[12];
    const float* k1  = (const float*)d_in[13];
    const float* kb1 = (const float*)d_in[14];
    const float* k2  = (const float*)d_in[15];
    const float* kb2 = (const float*)d_in[16];
    const float* k3  = (const float*)d_in[17];
    const float* kb3 = (const float*)d_in[18];
    float* out = (float*)d_out;

    float *stacked, *y, *ytmp, *sbase, *h1, *h2, *apA, *apB, *amax, *filt, *gb;
    double* part;
    cudaGetSymbolAddress((void**)&stacked, g_stacked);
    cudaGetSymbolAddress((void**)&y,       g_y);
    cudaGetSymbolAddress((void**)&ytmp,    g_ytmp);
    cudaGetSymbolAddress((void**)&sbase,   g_s);
    cudaGetSymbolAddress((void**)&h1,      g_h1);
    cudaGetSymbolAddress((void**)&h2,      g_h2);
    cudaGetSymbolAddress((void**)&apA,     g_apA);
    cudaGetSymbolAddress((void**)&apB,     g_apB);
    cudaGetSymbolAddress((void**)&amax,    g_amax);
    cudaGetSymbolAddress((void**)&filt,    g_filt);
    cudaGetSymbolAddress((void**)&gb,      g_gb);
    cudaGetSymbolAddress((void**)&part,    g_part);

    float* S[6];
    for (int k = 0; k < 6; k++) S[k] = sbase + (size_t)k * NN_;

    // ---- wavelet decomposition ----
    kcopyx<<<NC_/256, 256>>>(x, stacked);
    const float* cur = x;
    float* nxt = apA;
    for (int lvl = 0; lvl < 3; lvl++){
        kmax<<<B_*C_, 256>>>(cur, amax);
        kdywan<<<1, 256>>>(amax, sw1, sb1, sw2, sb2, sw3, sb3, filt);
        kwav<<<NC_/256, 256>>>(cur, filt, nxt, stacked, (lvl+1)*64);
        cur = nxt;
        nxt = (nxt == apA) ? apB : apA;
    }
    cudaMemcpyAsync(y, stacked, (size_t)NN_ * sizeof(float), cudaMemcpyDeviceToDevice, 0);

    // ---- gamma/beta for all 25 evals ----
    kgb<<<NEVAL_, 128>>>(tw1, tb1, tw2, tb2, cw, cb, gb);

    auto odef = [&](int ev, const float* yin, float* sout){
        kconv<256,128,true ,true ><<<dim3(L_/32, B_, 8),  dim3(32,8)>>>(yin, k1, kb1, gb + ev*128, h1, 64);
        kconv< 64, 64,false,true ><<<dim3(L_/32, B_, 8),  dim3(32,8)>>>(h1,  k2, kb2, nullptr,     h2, 64);
        kconv< 64, 64,false,false><<<dim3(L_/32, B_, 32), dim3(32,8)>>>(h2,  k3, kb3, nullptr,     sout, 256);
    };

    const double hs = 0.25;
    const int GB = NN_/256;
    for (int st = 0; st < 4; st++){
        int e = st*6;
        odef(e+0, y, S[0]);
        kcomb<<<GB,256>>>(ytmp, y, S[0], (float)(hs*1.0/5.0),
                          nullptr,0.f, nullptr,0.f, nullptr,0.f, nullptr,0.f, nullptr,0.f);
        odef(e+1, ytmp, S[1]);
        kcomb<<<GB,256>>>(ytmp, y, S[0], (float)(hs*3.0/40.0), S[1], (float)(hs*9.0/40.0),
                          nullptr,0.f, nullptr,0.f, nullptr,0.f, nullptr,0.f);
        odef(e+2, ytmp, S[2]);
        kcomb<<<GB,256>>>(ytmp, y, S[0], (float)(hs*44.0/45.0), S[1], (float)(-hs*56.0/15.0),
                          S[2], (float)(hs*32.0/9.0), nullptr,0.f, nullptr,0.f, nullptr,0.f);
        odef(e+3, ytmp, S[3]);
        kcomb<<<GB,256>>>(ytmp, y, S[0], (float)(hs*19372.0/6561.0), S[1], (float)(-hs*25360.0/2187.0),
                          S[2], (float)(hs*64448.0/6561.0), S[3], (float)(-hs*212.0/729.0),
                          nullptr,0.f, nullptr,0.f);
        odef(e+4, ytmp, S[4]);
        kcomb<<<GB,256>>>(ytmp, y, S[0], (float)(hs*9017.0/3168.0), S[1], (float)(-hs*355.0/33.0),
                          S[2], (float)(hs*46732.0/5247.0), S[3], (float)(hs*49.0/176.0),
                          S[4], (float)(-hs*5103.0/18656.0), nullptr,0.f);
        odef(e+5, ytmp, S[5]);
        kcomb<<<GB,256>>>(y, y, S[0], (float)(hs*35.0/384.0), S[2], (float)(hs*500.0/1113.0),
                          S[3], (float)(hs*125.0/192.0), S[4], (float)(-hs*2187.0/6784.0),
                          S[5], (float)(hs*11.0/84.0), nullptr,0.f);
    }

    // ---- dx = ode_f(1.0, ode_out) ; ecloss ----
    odef(24, y, S[0]);
    kinner<<<dim3(B_, 64), 256>>>(stacked, S[0], part);

    // ---- outputs ----
    kout<<<GB, 256>>>(y, out);
    kfinal<<<1, 32>>>(part, out);
}

// round 2
// speedup vs baseline: 1.5016x; 1.5016x over previous
#include <cuda_runtime.h>
#include <math.h>

#define B_ 8
#define C_ 64
#define L_ 2048
#define CS_ 256
#define HD_ 64
#define NN_ (B_*CS_*L_)      // 4194304
#define NC_ (B_*C_*L_)       // 1048576
#define NEVAL_ 25
#define CIC_ 32

// ---------------- scratch (device globals; no runtime allocation) ----------------
__device__ float g_stacked[NN_];
__device__ float g_y[NN_];
__device__ float g_s[6][NN_];
__device__ float g_h1[B_*HD_*L_];
__device__ float g_h2[B_*HD_*L_];
__device__ float g_apA[NC_];
__device__ float g_apB[NC_];
__device__ float g_amax[B_*C_];
__device__ float g_filt[16];
__device__ float g_gb[NEVAL_*128];
__device__ double g_part[B_*64];

__device__ __forceinline__ float gelu_f(float x){
    return 0.5f * x * (1.0f + erff(x * 0.70710678118654752440f));
}

// ---------------- wavelet part ----------------
__global__ void kcopyx(const float* __restrict__ x, float* __restrict__ stacked){
    int i = blockIdx.x*256 + threadIdx.x;
    int l = i & (L_-1); int bc = i >> 11; int c = bc & 63; int b = bc >> 6;
    stacked[(((b*CS_) + c) << 11) + l] = x[i];
}

__global__ void kmax(const float* __restrict__ src, float* __restrict__ amax){
    int row = blockIdx.x;
    const float* p = src + (size_t)row * L_;
    float m = -3.4e38f;
    for (int i = threadIdx.x; i < L_; i += 256) m = fmaxf(m, p[i]);
    __shared__ float sm[256];
    sm[threadIdx.x] = m; __syncthreads();
    for (int s = 128; s > 0; s >>= 1){
        if (threadIdx.x < s) sm[threadIdx.x] = fmaxf(sm[threadIdx.x], sm[threadIdx.x+s]);
        __syncthreads();
    }
    if (threadIdx.x == 0) amax[row] = sm[0];
}

__global__ void kdywan(const float* __restrict__ amax,
                       const float* __restrict__ sw1, const float* __restrict__ sb1,
                       const float* __restrict__ sw2, const float* __restrict__ sb2,
                       const float* __restrict__ sw3, const float* __restrict__ sb3,
                       float* __restrict__ filt){
    __shared__ float feat[8*32], g2[8*32], raw[8*16], nrm[16];
    int t = threadIdx.x;
    { int b = t >> 5, h = t & 31;
      float s = sb1[h];
      const float* am = amax + b*64; const float* w = sw1 + h*64;
      #pragma unroll 8
      for (int c = 0; c < 64; c++) s += am[c]*w[c];
      feat[t] = gelu_f(s); }
    __syncthreads();
    { int b = t >> 5, h = t & 31;
      float s = sb2[h];
      #pragma unroll 8
      for (int k = 0; k < 32; k++) s += feat[b*32+k]*sw2[h*32+k];
      g2[t] = gelu_f(s); }
    __syncthreads();
    if (t < 128){ int b = t >> 4, j = t & 15;
      float s = sb3[j];
      #pragma unroll 8
      for (int k = 0; k < 32; k++) s += g2[b*32+k]*sw3[j*32+k];
      raw[t] = s; }
    __syncthreads();
    if (t < 16){ int b = t >> 1, hh = t & 1;
      float s = 0.f;
      for (int j = 0; j < 8; j++){ float v = raw[b*16 + hh*8 + j]; s += v*v; }
      nrm[t] = sqrtf(s); }
    __syncthreads();
    if (t < 16){ int hh = t >> 3, j = t & 7;
      float s = 0.f;
      for (int b = 0; b < 8; b++) s += raw[b*16 + hh*8 + j] / nrm[b*2 + hh];
      filt[hh*8 + j] = s * 0.125f; }
}

__global__ void kwav(const float* __restrict__ src, const float* __restrict__ filt,
                     float* __restrict__ apOut, float* __restrict__ stacked, int chOff){
    int i = blockIdx.x*256 + threadIdx.x;
    int l = i & (L_-1); int bc = i >> 11; int c = bc & 63; int b = bc >> 6;
    const float* row = src + (size_t)bc * L_;
    float alo = 0.f, ahi = 0.f;
    #pragma unroll
    for (int k = 0; k < 8; k++){
        int o = l + k - 3;
        if (o < 0) o = -o;
        if (o >= L_) o = 2*L_ - 2 - o;
        float v = row[o];
        alo += v * filt[k];
        ahi += v * filt[8 + k];
    }
    apOut[i] = alo;
    stacked[(((size_t)b*CS_ + chOff + c) << 11) + l] = ahi;
}

// ---------------- time MLP: gamma/beta for all 25 evals ----------------
__global__ void kgb(const float* __restrict__ tw1, const float* __restrict__ tb1,
                    const float* __restrict__ tw2, const float* __restrict__ tb2,
                    const float* __restrict__ cw,  const float* __restrict__ cb,
                    float* __restrict__ gb){
    int e = blockIdx.x;
    const double hs = 0.25;
    double td;
    if (e == 24) td = 1.0;
    else {
        int i = e / 6, s = e % 6;
        double off;
        switch (s){
            case 0: off = 0.0; break;
            case 1: off = hs/5.0; break;
            case 2: off = 3.0*hs/10.0; break;
            case 3: off = 4.0*hs/5.0; break;
            case 4: off = 8.0*hs/9.0; break;
            default: off = hs; break;
        }
        td = (double)i*hs + off;
    }
    float t = (float)td;
    __shared__ float te1[16], te2[16];
    int tid = threadIdx.x;
    if (tid < 16) te1[tid] = gelu_f(t * tw1[tid] + tb1[tid]);
    __syncthreads();
    if (tid < 16){
        float s = tb2[tid];
        #pragma unroll
        for (int k = 0; k < 16; k++) s += te1[k]*tw2[tid*16+k];
        te2[tid] = s;
    }
    __syncthreads();
    float s = cb[tid];
    #pragma unroll
    for (int k = 0; k < 16; k++) s += te2[k]*cw[tid*16+k];
    gb[e*128 + tid] = s;
}

// ---------------- register-tiled K=3 conv1d (pad=1) ----------------
// block tile: 64 co x 64 l; 256 threads; each thread 4 co x 4 l.
// fused input combination: in + c1*a1 + ... + c5*a5 (nullptr-terminated usage)
template<int CIN, bool FILM, bool DOGELU>
__global__ __launch_bounds__(256)
void kconv(const float* __restrict__ in,
           const float* __restrict__ a1, float c1,
           const float* __restrict__ a2, float c2,
           const float* __restrict__ a3, float c3,
           const float* __restrict__ a4, float c4,
           const float* __restrict__ a5, float c5,
           const float* __restrict__ w, const float* __restrict__ bias,
           const float* __restrict__ gb, float* __restrict__ out, int coTotal){
    __shared__ __align__(16) float xs[CIC_][68];
    __shared__ __align__(16) float ws[CIC_][3][64];

    const int b = blockIdx.y;
    const int lbase  = blockIdx.x * 64;
    const int cobase = blockIdx.z * 64;
    const int t  = threadIdx.x;
    const int ct = t & 15;
    const int lt = t >> 4;
    const int co0 = ct * 4;
    const int l0  = lt * 4;

    float acc[4][4];
    #pragma unroll
    for (int i = 0; i < 4; i++)
        #pragma unroll
        for (int j = 0; j < 4; j++) acc[i][j] = 0.f;

    const size_t inOff = (size_t)b * CIN * L_;
    const float* ib = in + inOff;
    const float* b1 = a1 ? a1 + inOff : nullptr;
    const float* b2 = a2 ? a2 + inOff : nullptr;
    const float* b3 = a3 ? a3 + inOff : nullptr;
    const float* b4 = a4 ? a4 + inOff : nullptr;
    const float* b5 = a5 ? a5 + inOff : nullptr;

    for (int c0 = 0; c0 < CIN; c0 += CIC_){
        // x tile (with halo, combined input)
        for (int idx = t; idx < CIC_*66; idx += 256){
            int ci = idx / 66, j = idx - ci*66;
            int gl = lbase - 1 + j;
            float v = 0.f;
            if (gl >= 0 && gl < L_){
                size_t o = (size_t)(c0 + ci) * L_ + gl;
                v = ib[o];
                if (b1) v += c1 * b1[o];
                if (b2) v += c2 * b2[o];
                if (b3) v += c3 * b3[o];
                if (b4) v += c4 * b4[o];
                if (b5) v += c5 * b5[o];
            }
            xs[ci][j] = v;
        }
        // weight tile: ws[ci][k][co]
        const float* wb = w + ((size_t)cobase * CIN + c0) * 3;
        for (int idx = t; idx < CIC_*192; idx += 256){
            int co = idx & 63; int r = idx >> 6;
            int k = r % 3; int ci = r / 3;
            ws[ci][k][co] = wb[(size_t)co * CIN * 3 + ci*3 + k];
        }
        __syncthreads();

        #pragma unroll 8
        for (int ci = 0; ci < CIC_; ci++){
            float4 xa = *(const float4*)&xs[ci][l0];
            float2 xb = *(const float2*)&xs[ci][l0 + 4];
            float xv[6] = {xa.x, xa.y, xa.z, xa.w, xb.x, xb.y};
            #pragma unroll
            for (int k = 0; k < 3; k++){
                float4 wv = *(const float4*)&ws[ci][k][co0];
                float wf[4] = {wv.x, wv.y, wv.z, wv.w};
                #pragma unroll
                for (int cc = 0; cc < 4; cc++)
                    #pragma unroll
                    for (int ll = 0; ll < 4; ll++)
                        acc[cc][ll] += wf[cc] * xv[ll + k];
            }
        }
        __syncthreads();
    }

    // epilogue
    #pragma unroll
    for (int cc = 0; cc < 4; cc++){
        int co = cobase + co0 + cc;
        float bia = bias[co];
        float ga = 0.f, be = 0.f;
        if (FILM){ ga = gb[co]; be = gb[64 + co]; }
        float4 r;
        float* pr = (float*)&r;
        #pragma unroll
        for (int ll = 0; ll < 4; ll++){
            float h = acc[cc][ll] + bia;
            if (FILM) h = (1.f + ga) * h + be;
            if (DOGELU) h = gelu_f(h);
            pr[ll] = h;
        }
        *(float4*)&out[((size_t)(b*coTotal + co)) * L_ + lbase + l0] = r;
    }
}

// ---------------- stage combination (only for y updates) ----------------
__global__ void kcomb(float* __restrict__ dst, const float* __restrict__ y,
                      const float* __restrict__ s1, float c1,
                      const float* __restrict__ s2, float c2,
                      const float* __restrict__ s3, float c3,
                      const float* __restrict__ s4, float c4,
                      const float* __restrict__ s5, float c5){
    int i = blockIdx.x*256 + threadIdx.x;
    float v = y[i] + c1*s1[i] + c2*s2[i] + c3*s3[i] + c4*s4[i] + c5*s5[i];
    dst[i] = v;
}

// ---------------- ecloss reduction ----------------
__global__ void kinner(const float* __restrict__ a, const float* __restrict__ d,
                       double* __restrict__ part){
    int bb = blockIdx.x, ch = blockIdx.y;
    size_t base = (size_t)bb*CS_*L_ + (size_t)ch*8192;
    double s = 0.0;
    for (int i = threadIdx.x; i < 8192; i += 256)
        s += (double)a[base+i] * (double)d[base+i];
    __shared__ double sm[256];
    sm[threadIdx.x] = s; __syncthreads();
    for (int st = 128; st > 0; st >>= 1){
        if (threadIdx.x < st) sm[threadIdx.x] += sm[threadIdx.x+st];
        __syncthreads();
    }
    if (threadIdx.x == 0) part[bb*64 + ch] = sm[0];
}

__global__ void kfinal(const double* __restrict__ part, float* __restrict__ out){
    if (threadIdx.x == 0){
        double acc = 0.0;
        for (int b = 0; b < 8; b++){
            double s = 0.0;
            for (int j = 0; j < 64; j++) s += part[b*64+j];
            acc += s*s;
        }
        out[4194304] = (float)(acc / 8.0);
    }
}

// ---------------- output permute ----------------
__global__ void kout(const float* __restrict__ y, float* __restrict__ out){
    int i = blockIdx.x*256 + threadIdx.x;
    int l = i & (L_-1); int bc = i >> 11; int c = bc & 255; int b = bc >> 8;
    int g = c >> 6; int cc = c & 63;
    out[(size_t)g*(B_*C_*L_) + (((size_t)b*C_ + cc) << 11) + l] = y[i];
}

// ---------------- host orchestration ----------------
extern "C" void kernel_launch(void* const* d_in, const int* in_sizes, int n_in,
                              void* d_out, int out_size){
    const float* x   = (const float*)d_in[0];
    const float* sw1 = (const float*)d_in[1];
    const float* sb1 = (const float*)d_in[2];
    const float* sw2 = (const float*)d_in[3];
    const float* sb2 = (const float*)d_in[4];
    const float* sw3 = (const float*)d_in[5];
    const float* sb3 = (const float*)d_in[6];
    const float* tw1 = (const float*)d_in[7];
    const float* tb1 = (const float*)d_in[8];
    const float* tw2 = (const float*)d_in[9];
    const float* tb2 = (const float*)d_in[10];
    const float* cw  = (const float*)d_in[11];
    const float* cb  = (const float*)d_in[12];
    const float* k1  = (const float*)d_in[13];
    const float* kb1 = (const float*)d_in[14];
    const float* k2  = (const float*)d_in[15];
    const float* kb2 = (const float*)d_in[16];
    const float* k3  = (const float*)d_in[17];
    const float* kb3 = (const float*)d_in[18];
    float* out = (float*)d_out;

    float *stacked, *y, *sbase, *h1, *h2, *apA, *apB, *amax, *filt, *gb;
    double* part;
    cudaGetSymbolAddress((void**)&stacked, g_stacked);
    cudaGetSymbolAddress((void**)&y,       g_y);
    cudaGetSymbolAddress((void**)&sbase,   g_s);
    cudaGetSymbolAddress((void**)&h1,      g_h1);
    cudaGetSymbolAddress((void**)&h2,      g_h2);
    cudaGetSymbolAddress((void**)&apA,     g_apA);
    cudaGetSymbolAddress((void**)&apB,     g_apB);
    cudaGetSymbolAddress((void**)&amax,    g_amax);
    cudaGetSymbolAddress((void**)&filt,    g_filt);
    cudaGetSymbolAddress((void**)&gb,      g_gb);
    cudaGetSymbolAddress((void**)&part,    g_part);

    float* S[6];
    for (int k = 0; k < 6; k++) S[k] = sbase + (size_t)k * NN_;

    // ---- wavelet decomposition ----
    kcopyx<<<NC_/256, 256>>>(x, stacked);
    const float* cur = x;
    float* nxt = apA;
    for (int lvl = 0; lvl < 3; lvl++){
        kmax<<<B_*C_, 256>>>(cur, amax);
        kdywan<<<1, 256>>>(amax, sw1, sb1, sw2, sb2, sw3, sb3, filt);
        kwav<<<NC_/256, 256>>>(cur, filt, nxt, stacked, (lvl+1)*64);
        cur = nxt;
        nxt = (nxt == apA) ? apB : apA;
    }
    cudaMemcpyAsync(y, stacked, (size_t)NN_ * sizeof(float), cudaMemcpyDeviceToDevice, 0);

    kgb<<<NEVAL_, 128>>>(tw1, tb1, tw2, tb2, cw, cb, gb);

    const dim3 g1(L_/64, B_, 1), g3(L_/64, B_, 4), blk(256);

    // ode_f with fused input combination: input = y + Σ ck*sk
    auto odef = [&](int ev, const float* a1, float c1, const float* a2, float c2,
                    const float* a3, float c3, const float* a4, float c4,
                    const float* a5, float c5, float* sout){
        kconv<256,true ,true ><<<g1, blk>>>(y, a1,c1, a2,c2, a3,c3, a4,c4, a5,c5,
                                            k1, kb1, gb + ev*128, h1, 64);
        kconv< 64,false,true ><<<g1, blk>>>(h1, nullptr,0.f, nullptr,0.f, nullptr,0.f,
                                            nullptr,0.f, nullptr,0.f,
                                            k2, kb2, nullptr, h2, 64);
        kconv< 64,false,false><<<g3, blk>>>(h2, nullptr,0.f, nullptr,0.f, nullptr,0.f,
                                            nullptr,0.f, nullptr,0.f,
                                            k3, kb3, nullptr, sout, 256);
    };

    const double hs = 0.25;
    const int GB = NN_/256;
    const float* Z = nullptr;
    for (int st = 0; st < 4; st++){
        int e = st*6;
        odef(e+0, Z,0,Z,0,Z,0,Z,0,Z,0, S[0]);
        odef(e+1, S[0],(float)(hs*1.0/5.0), Z,0,Z,0,Z,0,Z,0, S[1]);
        odef(e+2, S[0],(float)(hs*3.0/40.0), S[1],(float)(hs*9.0/40.0), Z,0,Z,0,Z,0, S[2]);
        odef(e+3, S[0],(float)(hs*44.0/45.0), S[1],(float)(-hs*56.0/15.0),
                  S[2],(float)(hs*32.0/9.0), Z,0,Z,0, S[3]);
        odef(e+4, S[0],(float)(hs*19372.0/6561.0), S[1],(float)(-hs*25360.0/2187.0),
                  S[2],(float)(hs*64448.0/6561.0), S[3],(float)(-hs*212.0/729.0), Z,0, S[4]);
        odef(e+5, S[0],(float)(hs*9017.0/3168.0), S[1],(float)(-hs*355.0/33.0),
                  S[2],(float)(hs*46732.0/5247.0), S[3],(float)(hs*49.0/176.0),
                  S[4],(float)(-hs*5103.0/18656.0), S[5]);
        kcomb<<<GB,256>>>(y, y, S[0],(float)(hs*35.0/384.0), S[2],(float)(hs*500.0/1113.0),
                          S[3],(float)(hs*125.0/192.0), S[4],(float)(-hs*2187.0/6784.0),
                          S[5],(float)(hs*11.0/84.0));
    }

    // ---- dx = ode_f(1.0, ode_out) ; ecloss ----
    odef(24, Z,0,Z,0,Z,0,Z,0,Z,0, S[0]);
    kinner<<<dim3(B_, 64), 256>>>(stacked, S[0], part);

    // ---- outputs ----
    kout<<<GB, 256>>>(y, out);
    kfinal<<<1, 32>>>(part, out);
}